// round 1
// baseline (speedup 1.0000x reference)
#include <cuda_runtime.h>
#include <cstdint>

#define HH 256
#define WW 256
#define NC 80
#define HWSZ 65536
#define KTOP 100
#define MAXCAND 8192

// scratch (no cudaMalloc allowed)
__device__ unsigned int        g_count[NC];
__device__ unsigned long long  g_cand[NC][MAXCAND];
__device__ unsigned int        g_topk_key[NC * KTOP];   // fkey(logit)
__device__ int                 g_topk_idx[NC * KTOP];   // spatial index in [0,65536)

// monotone float->uint key (handles negatives)
__device__ __forceinline__ unsigned int fkey(float f) {
    unsigned int b = __float_as_uint(f);
    return b ^ ((b & 0x80000000u) ? 0xFFFFFFFFu : 0x80000000u);
}
__device__ __forceinline__ float fkeyinv(unsigned int k) {
    unsigned int b = k ^ ((k & 0x80000000u) ? 0x80000000u : 0xFFFFFFFFu);
    return __uint_as_float(b);
}

__global__ void zero_counts_kernel() {
    if (threadIdx.x < NC) g_count[threadIdx.x] = 0u;
}

// 5x5 strict-window max (SAME, -inf pad) on logits of batch 0; compact survivors.
__global__ void suppress_kernel(const float* __restrict__ cls) {
    __shared__ float t[36][36 + 1];
    __shared__ float rmax[36][32 + 1];
    const int c  = blockIdx.z;
    const int x0 = blockIdx.x * 32, y0 = blockIdx.y * 32;
    const float* p = cls + (size_t)c * HWSZ;   // batch 0
    const int tid = threadIdx.y * 32 + threadIdx.x;

    for (int i = tid; i < 36 * 36; i += 1024) {
        int ly = i / 36, lx = i % 36;
        int gy = y0 + ly - 2, gx = x0 + lx - 2;
        float v = -__int_as_float(0x7f800000);  // -inf
        if (gy >= 0 && gy < HH && gx >= 0 && gx < WW) v = p[gy * WW + gx];
        t[ly][lx] = v;
    }
    __syncthreads();
    for (int i = tid; i < 36 * 32; i += 1024) {
        int ly = i / 32, lx = i % 32;
        float m = t[ly][lx];
        m = fmaxf(m, t[ly][lx + 1]);
        m = fmaxf(m, t[ly][lx + 2]);
        m = fmaxf(m, t[ly][lx + 3]);
        m = fmaxf(m, t[ly][lx + 4]);
        rmax[ly][lx] = m;
    }
    __syncthreads();
    const int lx = threadIdx.x, ly = threadIdx.y;
    float v = t[ly + 2][lx + 2];
    float m = rmax[ly][lx];
    m = fmaxf(m, rmax[ly + 1][lx]);
    m = fmaxf(m, rmax[ly + 2][lx]);
    m = fmaxf(m, rmax[ly + 3][lx]);
    m = fmaxf(m, rmax[ly + 4][lx]);
    if (v == m) {
        int idx = (y0 + ly) * WW + (x0 + lx);
        unsigned int pos = atomicAdd(&g_count[c], 1u);
        if (pos < MAXCAND)
            g_cand[c][pos] = ((unsigned long long)fkey(v) << 32)
                           | (unsigned int)(65535 - idx);   // lower idx => bigger key tail
    }
}

// per-class bitonic sort (descending) of candidates, emit top-100
__global__ void class_topk_kernel() {
    extern __shared__ unsigned long long s[];
    const int c = blockIdx.x;
    unsigned int cnt = g_count[c];
    if (cnt > MAXCAND) cnt = MAXCAND;
    int n = 128;
    while (n < (int)cnt) n <<= 1;

    for (int i = threadIdx.x; i < n; i += blockDim.x)
        s[i] = (i < (int)cnt) ? g_cand[c][i] : 0ULL;
    __syncthreads();

    for (int k = 2; k <= n; k <<= 1) {
        for (int j = k >> 1; j > 0; j >>= 1) {
            for (int i = threadIdx.x; i < n; i += blockDim.x) {
                int ixj = i ^ j;
                if (ixj > i) {
                    unsigned long long a = s[i], b = s[ixj];
                    bool up = ((i & k) == 0);
                    if (up ? (a < b) : (a > b)) { s[i] = b; s[ixj] = a; }
                }
            }
            __syncthreads();
        }
    }
    for (int k = threadIdx.x; k < KTOP; k += blockDim.x) {
        unsigned long long key = s[k];
        g_topk_key[c * KTOP + k] = (unsigned int)(key >> 32);
        g_topk_idx[c * KTOP + k] = 65535 - (int)(key & 0xFFFFu);
    }
}

// global top-100 over 80*100 entries + box decode + output write
__global__ void global_topk_kernel(const float* __restrict__ txty,
                                   const float* __restrict__ twth,
                                   float* __restrict__ out) {
    extern __shared__ unsigned long long s[];
    const int N = 8192;
    for (int i = threadIdx.x; i < N; i += blockDim.x) {
        if (i < NC * KTOP)
            s[i] = ((unsigned long long)g_topk_key[i] << 32)
                 | (unsigned int)(8191 - i);               // lower flat idx first on ties
        else
            s[i] = 0ULL;
    }
    __syncthreads();
    for (int k = 2; k <= N; k <<= 1) {
        for (int j = k >> 1; j > 0; j >>= 1) {
            for (int i = threadIdx.x; i < N; i += blockDim.x) {
                int ixj = i ^ j;
                if (ixj > i) {
                    unsigned long long a = s[i], b = s[ixj];
                    bool up = ((i & k) == 0);
                    if (up ? (a < b) : (a > b)) { s[i] = b; s[ixj] = a; }
                }
            }
            __syncthreads();
        }
    }
    if (threadIdx.x < KTOP) {
        const int t = threadIdx.x;
        unsigned long long key = s[t];
        unsigned int kb = (unsigned int)(key >> 32);
        int flat = 8191 - (int)(key & 0x1FFFu);
        int cls = flat / KTOP;
        int spatial = g_topk_idx[flat];
        float logit = fkeyinv(kb);
        float score = 1.0f / (1.0f + expf(-logit));

        int y = spatial >> 8, x = spatial & 255;
        float tx = txty[spatial];              // batch0, ch0
        float ty = txty[HWSZ + spatial];       // batch0, ch1
        float tw = twth[spatial];
        float th = twth[HWSZ + spatial];

        float cx = ((float)x + 1.0f / (1.0f + expf(-tx))) * 4.0f;
        float cy = ((float)y + 1.0f / (1.0f + expf(-ty))) * 4.0f;
        float w2 = expf(tw) * 2.0f;   // exp*stride/2
        float h2 = expf(th) * 2.0f;
        const float inv = 1.0f / 1024.0f;

        out[t * 4 + 0] = fminf(fmaxf((cx - w2) * inv, 0.0f), 1.0f);
        out[t * 4 + 1] = fminf(fmaxf((cy - h2) * inv, 0.0f), 1.0f);
        out[t * 4 + 2] = fminf(fmaxf((cx + w2) * inv, 0.0f), 1.0f);
        out[t * 4 + 3] = fminf(fmaxf((cy + h2) * inv, 0.0f), 1.0f);
        out[4 * KTOP + t] = score;
        out[5 * KTOP + t] = (float)cls;
    }
}

extern "C" void kernel_launch(void* const* d_in, const int* in_sizes, int n_in,
                              void* d_out, int out_size) {
    const float* cls  = (const float*)d_in[0];
    const float* txty = (const float*)d_in[1];
    const float* twth = (const float*)d_in[2];
    float* out = (float*)d_out;

    cudaFuncSetAttribute(class_topk_kernel,
                         cudaFuncAttributeMaxDynamicSharedMemorySize, 65536);
    cudaFuncSetAttribute(global_topk_kernel,
                         cudaFuncAttributeMaxDynamicSharedMemorySize, 65536);

    zero_counts_kernel<<<1, 128>>>();
    dim3 grid(WW / 32, HH / 32, NC);
    dim3 blk(32, 32);
    suppress_kernel<<<grid, blk>>>(cls);
    class_topk_kernel<<<NC, 512, 65536>>>();
    global_topk_kernel<<<1, 1024, 65536>>>(txty, twth, out);
}

// round 2
// speedup vs baseline: 1.0069x; 1.0069x over previous
#include <cuda_runtime.h>
#include <cstdint>

#define HH 256
#define WW 256
#define NC 80
#define HWSZ 65536
#define KTOP 100
#define MAXCAND 8192

// scratch (no cudaMalloc allowed)
__device__ unsigned int        g_count[NC];
__device__ unsigned long long  g_cand[NC][MAXCAND];
__device__ unsigned int        g_topk_key[NC * KTOP];   // fkey(logit)
__device__ int                 g_topk_idx[NC * KTOP];   // spatial index in [0,65536)

// monotone float->uint key (handles negatives)
__device__ __forceinline__ unsigned int fkey(float f) {
    unsigned int b = __float_as_uint(f);
    return b ^ ((b & 0x80000000u) ? 0xFFFFFFFFu : 0x80000000u);
}
__device__ __forceinline__ float fkeyinv(unsigned int k) {
    unsigned int b = k ^ ((k & 0x80000000u) ? 0x80000000u : 0xFFFFFFFFu);
    return __uint_as_float(b);
}

__global__ void zero_counts_kernel() {
    if (threadIdx.x < NC) g_count[threadIdx.x] = 0u;
}

// 5x5 strict-window max (SAME, -inf pad) on logits of batch 0; compact survivors.
__global__ void suppress_kernel(const float* __restrict__ cls) {
    __shared__ float t[36][36 + 1];
    __shared__ float rmax[36][32 + 1];
    const int c  = blockIdx.z;
    const int x0 = blockIdx.x * 32, y0 = blockIdx.y * 32;
    const float* p = cls + (size_t)c * HWSZ;   // batch 0
    const int tid = threadIdx.y * 32 + threadIdx.x;

    for (int i = tid; i < 36 * 36; i += 1024) {
        int ly = i / 36, lx = i % 36;
        int gy = y0 + ly - 2, gx = x0 + lx - 2;
        float v = -__int_as_float(0x7f800000);  // -inf
        if (gy >= 0 && gy < HH && gx >= 0 && gx < WW) v = p[gy * WW + gx];
        t[ly][lx] = v;
    }
    __syncthreads();
    for (int i = tid; i < 36 * 32; i += 1024) {
        int ly = i / 32, lx = i % 32;
        float m = t[ly][lx];
        m = fmaxf(m, t[ly][lx + 1]);
        m = fmaxf(m, t[ly][lx + 2]);
        m = fmaxf(m, t[ly][lx + 3]);
        m = fmaxf(m, t[ly][lx + 4]);
        rmax[ly][lx] = m;
    }
    __syncthreads();
    const int lx = threadIdx.x, ly = threadIdx.y;
    float v = t[ly + 2][lx + 2];
    float m = rmax[ly][lx];
    m = fmaxf(m, rmax[ly + 1][lx]);
    m = fmaxf(m, rmax[ly + 2][lx]);
    m = fmaxf(m, rmax[ly + 3][lx]);
    m = fmaxf(m, rmax[ly + 4][lx]);
    if (v == m) {
        int idx = (y0 + ly) * WW + (x0 + lx);
        unsigned int pos = atomicAdd(&g_count[c], 1u);
        if (pos < MAXCAND)
            g_cand[c][pos] = ((unsigned long long)fkey(v) << 32)
                           | (unsigned int)(65535 - idx);   // lower idx => bigger key tail
    }
}

// per-class bitonic sort (descending) of candidates, emit top-100
__global__ void class_topk_kernel() {
    extern __shared__ unsigned long long s[];
    const int c = blockIdx.x;
    unsigned int cnt = g_count[c];
    if (cnt > MAXCAND) cnt = MAXCAND;
    int n = 128;
    while (n < (int)cnt) n <<= 1;

    for (int i = threadIdx.x; i < n; i += blockDim.x)
        s[i] = (i < (int)cnt) ? g_cand[c][i] : 0ULL;
    __syncthreads();

    for (int k = 2; k <= n; k <<= 1) {
        for (int j = k >> 1; j > 0; j >>= 1) {
            for (int i = threadIdx.x; i < n; i += blockDim.x) {
                int ixj = i ^ j;
                if (ixj > i) {
                    unsigned long long a = s[i], b = s[ixj];
                    bool up = ((i & k) == 0);
                    if (up ? (a < b) : (a > b)) { s[i] = b; s[ixj] = a; }
                }
            }
            __syncthreads();
        }
    }
    for (int k = threadIdx.x; k < KTOP; k += blockDim.x) {
        unsigned long long key = s[k];
        g_topk_key[c * KTOP + k] = (unsigned int)(key >> 32);
        g_topk_idx[c * KTOP + k] = 65535 - (int)(key & 0xFFFFu);
    }
}

// global top-100 over 80*100 entries + box decode + output write
__global__ void global_topk_kernel(const float* __restrict__ txty,
                                   const float* __restrict__ twth,
                                   float* __restrict__ out) {
    extern __shared__ unsigned long long s[];
    const int N = 8192;
    for (int i = threadIdx.x; i < N; i += blockDim.x) {
        if (i < NC * KTOP)
            s[i] = ((unsigned long long)g_topk_key[i] << 32)
                 | (unsigned int)(8191 - i);               // lower flat idx first on ties
        else
            s[i] = 0ULL;
    }
    __syncthreads();
    for (int k = 2; k <= N; k <<= 1) {
        for (int j = k >> 1; j > 0; j >>= 1) {
            for (int i = threadIdx.x; i < N; i += blockDim.x) {
                int ixj = i ^ j;
                if (ixj > i) {
                    unsigned long long a = s[i], b = s[ixj];
                    bool up = ((i & k) == 0);
                    if (up ? (a < b) : (a > b)) { s[i] = b; s[ixj] = a; }
                }
            }
            __syncthreads();
        }
    }
    if (threadIdx.x < KTOP) {
        const int t = threadIdx.x;
        unsigned long long key = s[t];
        unsigned int kb = (unsigned int)(key >> 32);
        int flat = 8191 - (int)(key & 0x1FFFu);
        int cls = flat / KTOP;
        int spatial = g_topk_idx[flat];
        float logit = fkeyinv(kb);
        float score = 1.0f / (1.0f + expf(-logit));

        int y = spatial >> 8, x = spatial & 255;
        float tx = txty[spatial];              // batch0, ch0
        float ty = txty[HWSZ + spatial];       // batch0, ch1
        float tw = twth[spatial];
        float th = twth[HWSZ + spatial];

        float cx = ((float)x + 1.0f / (1.0f + expf(-tx))) * 4.0f;
        float cy = ((float)y + 1.0f / (1.0f + expf(-ty))) * 4.0f;
        float w2 = expf(tw) * 2.0f;   // exp*stride/2
        float h2 = expf(th) * 2.0f;
        const float inv = 1.0f / 1024.0f;

        out[t * 4 + 0] = fminf(fmaxf((cx - w2) * inv, 0.0f), 1.0f);
        out[t * 4 + 1] = fminf(fmaxf((cy - h2) * inv, 0.0f), 1.0f);
        out[t * 4 + 2] = fminf(fmaxf((cx + w2) * inv, 0.0f), 1.0f);
        out[t * 4 + 3] = fminf(fmaxf((cy + h2) * inv, 0.0f), 1.0f);
        out[4 * KTOP + t] = score;
        out[5 * KTOP + t] = (float)cls;
    }
}

extern "C" void kernel_launch(void* const* d_in, const int* in_sizes, int n_in,
                              void* d_out, int out_size) {
    const float* cls  = (const float*)d_in[0];
    const float* txty = (const float*)d_in[1];
    const float* twth = (const float*)d_in[2];
    float* out = (float*)d_out;

    cudaFuncSetAttribute(class_topk_kernel,
                         cudaFuncAttributeMaxDynamicSharedMemorySize, 65536);
    cudaFuncSetAttribute(global_topk_kernel,
                         cudaFuncAttributeMaxDynamicSharedMemorySize, 65536);

    zero_counts_kernel<<<1, 128>>>();
    dim3 grid(WW / 32, HH / 32, NC);
    dim3 blk(32, 32);
    suppress_kernel<<<grid, blk>>>(cls);
    class_topk_kernel<<<NC, 512, 65536>>>();
    global_topk_kernel<<<1, 1024, 65536>>>(txty, twth, out);
}